// round 11
// baseline (speedup 1.0000x reference)
#include <cuda_runtime.h>
#include <cuda_bf16.h>
#include <cuda_fp16.h>
#include <cstddef>
#include <cstdint>

// ---------------------------------------------------------------------------
// Problem constants
// ---------------------------------------------------------------------------
#define NMAX   200000
#define EMAX   650000
#define EMB    128
#define ENC1   256
#define NEG_SLOPE 0.1f
#define LN_EPS 1e-5f

// ---------------------------------------------------------------------------
// Scratch (static __device__ arrays; no allocations allowed)
// ---------------------------------------------------------------------------
__device__ float g_H[4][(size_t)NMAX * EMB];   // h_list[0..3]
__device__ float g_XL[(size_t)NMAX * EMB];     // pass-B init buffer
__device__ float g_AGG[(size_t)NMAX * EMB];    // pass-A init buffer
__device__ float g_H1[(size_t)NMAX * ENC1];    // encoder intermediate
__device__ __half2 g_YA[(size_t)NMAX * 64];    // fp16 messages, pass A
__device__ __half2 g_YB[(size_t)NMAX * 64];    // fp16 messages, pass B
__device__ float g_disA[NMAX];
__device__ float g_disB[NMAX];
__device__ float g_invA[NMAX];
__device__ float g_invB[NMAX];
// CSR scratch: [0,N) rowcntA | [N,2N) rowcntB | [2N,4N) colcnt (A then B)
//              [4N,6N) cursors (A then B)
__device__ int g_icsr[6 * NMAX];
__device__ int g_offs[2 * NMAX];
__device__ int g_src[2 * EMAX];
__device__ int g_bsums[512];
// Prepped weight chunks: 18 chunks of [128 n x 64 k] bf16, XOR-swizzled, hi/lo.
__device__ __nv_bfloat16 g_Bhi[18 * 8192];
__device__ __nv_bfloat16 g_Blo[18 * 8192];

// ---------------------------------------------------------------------------
// Helpers
// ---------------------------------------------------------------------------
__device__ __forceinline__ float leaky(float v) {
    return v >= 0.0f ? v : NEG_SLOPE * v;
}
__device__ __forceinline__ float relu_(float v) { return fmaxf(v, 0.0f); }

__device__ __forceinline__ uint32_t smem_u32(const void* p) {
    uint32_t a;
    asm("{ .reg .u64 t; cvta.to.shared.u64 t, %1; cvt.u32.u64 %0, t; }"
        : "=r"(a) : "l"(p));
    return a;
}

__device__ __forceinline__ void ldsm4(uint32_t* r, uint32_t addr) {
    asm volatile("ldmatrix.sync.aligned.m8n8.x4.shared.b16 {%0,%1,%2,%3}, [%4];"
                 : "=r"(r[0]), "=r"(r[1]), "=r"(r[2]), "=r"(r[3]) : "r"(addr));
}

__device__ __forceinline__ void mma16816(float* c, const uint32_t* a,
                                         uint32_t b0, uint32_t b1) {
    asm volatile(
        "mma.sync.aligned.m16n8k16.row.col.f32.bf16.bf16.f32 "
        "{%0,%1,%2,%3}, {%4,%5,%6,%7}, {%8,%9}, {%0,%1,%2,%3};"
        : "+f"(c[0]), "+f"(c[1]), "+f"(c[2]), "+f"(c[3])
        : "r"(a[0]), "r"(a[1]), "r"(a[2]), "r"(a[3]), "r"(b0), "r"(b1));
}

// fp32x4 -> swizzled bf16 hi/lo store (packed converts)
__device__ __forceinline__ void store_hilo(char* smbase, int off, float4 v) {
    __nv_bfloat162 h01 = __float22bfloat162_rn(make_float2(v.x, v.y));
    __nv_bfloat162 h23 = __float22bfloat162_rn(make_float2(v.z, v.w));
    float2 hf01 = __bfloat1622float2(h01);
    float2 hf23 = __bfloat1622float2(h23);
    __nv_bfloat162 l01 = __float22bfloat162_rn(make_float2(v.x - hf01.x, v.y - hf01.y));
    __nv_bfloat162 l23 = __float22bfloat162_rn(make_float2(v.z - hf23.x, v.w - hf23.y));
    uint2 hi = make_uint2(*reinterpret_cast<uint32_t*>(&h01),
                          *reinterpret_cast<uint32_t*>(&h23));
    uint2 lo = make_uint2(*reinterpret_cast<uint32_t*>(&l01),
                          *reinterpret_cast<uint32_t*>(&l23));
    *(uint2*)(smbase + 0     + off) = hi;   // SM_A_HI == 0
    *(uint2*)(smbase + 16384 + off) = lo;   // SM_A_LO == 16384
}

// ---------------------------------------------------------------------------
// CSR build kernels
// ---------------------------------------------------------------------------
__global__ void zero_kernel(int* p, int n) {
    int i = blockIdx.x * blockDim.x + threadIdx.x;
    if (i < n) p[i] = 0;
}

__global__ void hist2_kernel(const int* __restrict__ rows,
                             const int* __restrict__ cols,
                             int* __restrict__ rowcnt,
                             int* __restrict__ colcnt, int E) {
    int e = blockIdx.x * blockDim.x + threadIdx.x;
    if (e >= E) return;
    atomicAdd(&rowcnt[rows[e]], 1);
    atomicAdd(&colcnt[cols[e]], 1);
}

__global__ void deg_fin_kernel(const int* __restrict__ cnt,
                               float* __restrict__ dis,
                               float* __restrict__ inv, int n) {
    int i = blockIdx.x * blockDim.x + threadIdx.x;
    if (i < n) {
        float d = (float)(cnt[i] + 1);
        dis[i] = rsqrtf(d);
        inv[i] = 1.0f / d;
    }
}

__global__ void scan_block_kernel(const int* __restrict__ in, int* __restrict__ out,
                                  int* __restrict__ bsums, int n) {
    __shared__ int sh[256];
    const int base = blockIdx.x * 1024;
    const int t = threadIdx.x;
    int v[4]; int s = 0;
#pragma unroll
    for (int j = 0; j < 4; j++) {
        int i = base + t * 4 + j;
        v[j] = (i < n) ? in[i] : 0;
        s += v[j];
    }
    sh[t] = s;
    __syncthreads();
    for (int off = 1; off < 256; off <<= 1) {
        int x = (t >= off) ? sh[t - off] : 0;
        __syncthreads();
        sh[t] += x;
        __syncthreads();
    }
    int run = (t > 0) ? sh[t - 1] : 0;
    if (t == 255) bsums[blockIdx.x] = sh[255];
#pragma unroll
    for (int j = 0; j < 4; j++) {
        int i = base + t * 4 + j;
        if (i < n) out[i] = run;
        run += v[j];
    }
}

__global__ void scan_sums_kernel(int* bsums, int nb) {
    __shared__ int sh[512];
    int t = threadIdx.x;
    sh[t] = (t < nb) ? bsums[t] : 0;
    __syncthreads();
    for (int off = 1; off < 512; off <<= 1) {
        int x = (t >= off) ? sh[t - off] : 0;
        __syncthreads();
        sh[t] += x;
        __syncthreads();
    }
    if (t < nb) bsums[t] = (t > 0) ? sh[t - 1] : 0;
}

__global__ void scan_add_kernel(int* __restrict__ out, const int* __restrict__ bsums,
                                int n) {
    int i = blockIdx.x * blockDim.x + threadIdx.x;
    if (i < n) out[i] += bsums[i >> 10];
}

__global__ void fill_kernel(const int* __restrict__ rows, const int* __restrict__ cols,
                            const int* __restrict__ offs, int* __restrict__ cursor,
                            int* __restrict__ src, int E, int obase) {
    int e = blockIdx.x * blockDim.x + threadIdx.x;
    if (e >= E) return;
    int c = cols[e];
    int pos = offs[obase + c] + atomicAdd(&cursor[obase + c], 1);
    src[pos] = rows[e];
}

// ---------------------------------------------------------------------------
// Merged weight prep: 18 chunks of [128n x 64k], swizzled bf16 hi/lo
// ---------------------------------------------------------------------------
__global__ void prep_all_kernel(const float* __restrict__ enc_w1,
                                const float* __restrict__ enc_w2,
                                const float* __restrict__ conv_w,
                                const float* __restrict__ reconv_w,
                                __nv_bfloat16* __restrict__ BH,
                                __nv_bfloat16* __restrict__ BL) {
    const int chunk = blockIdx.x >> 5;
    const int idx = (blockIdx.x & 31) * 256 + threadIdx.x;
    const int n = idx >> 6;
    const int k = idx & 63;
    const float* W; int ldn, k0, n0, kcount;
    if (chunk < 2)      { W = enc_w1; ldn = 256; k0 = 0; n0 = chunk * 128; kcount = 32; }
    else if (chunk < 6) { W = enc_w2; ldn = 128; k0 = (chunk - 2) * 64; n0 = 0; kcount = 64; }
    else if (chunk < 12) {
        int l = (chunk - 6) >> 1, c = (chunk - 6) & 1;
        W = conv_w + (size_t)l * 16384; ldn = 128; k0 = c * 64; n0 = 0; kcount = 64;
    } else {
        int l = (chunk - 12) >> 1, c = (chunk - 12) & 1;
        W = reconv_w + (size_t)l * 16384; ldn = 128; k0 = c * 64; n0 = 0; kcount = 64;
    }
    float v = (k < kcount) ? W[(size_t)(k0 + k) * ldn + n0 + n] : 0.0f;
    __nv_bfloat16 h = __float2bfloat16(v);
    __nv_bfloat16 l = __float2bfloat16(v - __bfloat162float(h));
    int off = n * 128 + ((k * 2) ^ ((n & 7) << 4));
    BH[(size_t)chunk * 8192 + (off >> 1)] = h;
    BL[(size_t)chunk * 8192 + (off >> 1)] = l;
}

// ---------------------------------------------------------------------------
// Tensor-core GEMM (mma.sync bf16 3-split): d = A @ W + bias
//  A-staging:
//    normal: A[M,KV] read from global (lda stride)
//    fused (yIn != null): A row r = initA[r] + adis[r] * sum_{CSR} yIn[src]
//  Epilogue:
//    mode 0: out[gr*ostride+colofs+n] = act? leaky(d) : d
//            if (aux && gr<rows_aux) also aux[gr*512+aofs+n]
//    mode 1: out[gr*128+n] = relu(d+root[n]) * inv[gr]  (init)
//            ybuf[gr][n]   = half( dis[gr] * relu(d) )  (message)
// ---------------------------------------------------------------------------
#define SM_A_HI 0
#define SM_A_LO 16384
#define SM_B_HI 32768
#define SM_B_LO 49152
#define SMEM_TC 65536

__global__ void __launch_bounds__(256, 2)
gemm_tc_kernel(const float* __restrict__ A, int lda, int M,
               const __nv_bfloat16* __restrict__ BhiG,
               const __nv_bfloat16* __restrict__ BloG,
               int kchunks, int KV,
               const float* __restrict__ bias,
               float* __restrict__ out, int ostride, int colofs, int act,
               float* __restrict__ aux, int aofs, int rows_aux,
               int mode,
               const float* __restrict__ root,
               const float* __restrict__ dis,
               const float* __restrict__ inv,
               __half2* __restrict__ ybuf,
               // fused-aggregation staging inputs (pass A):
               const float* __restrict__ initA,
               const __half2* __restrict__ yIn,
               const int* __restrict__ aoffs,
               const int* __restrict__ acnt,
               const int* __restrict__ asrc,
               const float* __restrict__ adis) {
    extern __shared__ char sm[];
    const uint32_t sb = smem_u32(sm);
    const int tid = threadIdx.x;
    const int w = tid >> 5;
    const int lane = tid & 31;
    const int wm = w & 3;
    const int wn = w >> 2;
    const int row0 = blockIdx.x * 128;

    float acc[2][8][4];
#pragma unroll
    for (int a = 0; a < 2; a++)
#pragma unroll
        for (int b = 0; b < 8; b++)
#pragma unroll
            for (int c = 0; c < 4; c++) acc[a][b][c] = 0.0f;

    for (int ck = 0; ck < kchunks; ck++) {
        const int kbase = ck * 64;
        int kcols = KV - kbase; if (kcols > 64) kcols = 64;
        const int ksteps = (kcols + 15) >> 4;

        // ---- stage B chunk ----
        {
            const float4* shg = (const float4*)(BhiG + (size_t)ck * 8192);
            const float4* slg = (const float4*)(BloG + (size_t)ck * 8192);
            float4* dh = (float4*)(sm + SM_B_HI);
            float4* dl = (float4*)(sm + SM_B_LO);
            for (int i = tid; i < 1024; i += 256) { dh[i] = shg[i]; dl[i] = slg[i]; }
        }

        // ---- stage A chunk ----
        if (yIn == nullptr) {
#pragma unroll
            for (int i = 0; i < 8; i++) {
                const int idx = tid + i * 256;
                const int r = idx >> 4;
                const int c4 = idx & 15;
                float4 v = make_float4(0.f, 0.f, 0.f, 0.f);
                const int gr = row0 + r;
                if (gr < M && c4 * 4 < kcols)
                    v = *(const float4*)(A + (size_t)gr * lda + kbase + c4 * 4);
                int off = r * 128 + ((c4 * 8) ^ ((r & 7) << 4));
                store_hilo(sm, off, v);
            }
        } else {
            // fused: half-warp per row; aggregate on the fly
            const int hw = lane >> 4;     // 0/1
            const int hl = lane & 15;     // col group
#pragma unroll
            for (int it = 0; it < 8; it++) {
                const int r = w * 16 + it * 2 + hw;
                const int gr = row0 + r;
                float4 v = make_float4(0.f, 0.f, 0.f, 0.f);
                if (gr < M) {
                    v = *(const float4*)(initA + (size_t)gr * 128 + kbase + hl * 4);
                    const int o = __ldg(aoffs + gr);
                    const int k = __ldg(acnt + gr);
                    const float dc = __ldg(adis + gr);
                    float4 na = make_float4(0.f, 0.f, 0.f, 0.f);
                    const __half2* ybase = yIn + (size_t)(kbase >> 1) + hl * 2;
                    for (int j = 0; j < k; j++) {
                        const int s = __ldg(asrc + o + j);
                        const uint2 y2 = *(const uint2*)(ybase + (size_t)s * 64);
                        float2 a0 = __half22float2(*(const __half2*)&y2.x);
                        float2 a1 = __half22float2(*(const __half2*)&y2.y);
                        na.x += a0.x; na.y += a0.y; na.z += a1.x; na.w += a1.y;
                    }
                    v.x += dc * na.x; v.y += dc * na.y;
                    v.z += dc * na.z; v.w += dc * na.w;
                }
                int off = r * 128 + ((hl * 8) ^ ((r & 7) << 4));
                store_hilo(sm, off, v);
            }
        }
        __syncthreads();

        // ---- compute ----
        for (int ks = 0; ks < ksteps; ks++) {
            uint32_t ah[2][4], al[2][4];
            {
                const int rr = (lane & 15);
                const int colb = ks * 32 + (lane & 16);
#pragma unroll
                for (int mt = 0; mt < 2; mt++) {
                    const int row = wm * 32 + mt * 16 + rr;
                    const uint32_t ad = (uint32_t)(row * 128 + (colb ^ ((row & 7) << 4)));
                    ldsm4(ah[mt], sb + SM_A_HI + ad);
                    ldsm4(al[mt], sb + SM_A_LO + ad);
                }
            }
#pragma unroll
            for (int np = 0; np < 4; np++) {
                const int nb = wn * 64 + np * 16;
                const int n = nb + (lane & 7) + ((lane & 16) >> 1);
                const int colb = ks * 32 + ((lane & 8) << 1);
                const uint32_t bd = (uint32_t)(n * 128 + (colb ^ ((n & 7) << 4)));
                uint32_t bh[4], bl[4];
                ldsm4(bh, sb + SM_B_HI + bd);
                ldsm4(bl, sb + SM_B_LO + bd);
#pragma unroll
                for (int mt = 0; mt < 2; mt++) {
#pragma unroll
                    for (int nt = 0; nt < 2; nt++) {
                        float* c = acc[mt][np * 2 + nt];
                        mma16816(c, ah[mt], bh[nt * 2], bh[nt * 2 + 1]);
                        mma16816(c, ah[mt], bl[nt * 2], bl[nt * 2 + 1]);
                        mma16816(c, al[mt], bh[nt * 2], bh[nt * 2 + 1]);
                    }
                }
            }
        }
        __syncthreads();
    }

    // ---- epilogue ----
    const int quad = lane >> 2;
    const int tq = lane & 3;
#pragma unroll
    for (int mt = 0; mt < 2; mt++) {
#pragma unroll
        for (int half = 0; half < 2; half++) {
            const int gr = row0 + wm * 32 + mt * 16 + half * 8 + quad;
            if (gr >= M) continue;
            if (mode == 0) {
                float* po = out + (size_t)gr * ostride + colofs + wn * 64;
                float* pa = (aux && gr < rows_aux)
                          ? aux + (size_t)gr * 512 + aofs + wn * 64 : nullptr;
#pragma unroll
                for (int j = 0; j < 8; j++) {
                    const int col = j * 8 + tq * 2;
                    float c0 = acc[mt][j][half * 2 + 0] + __ldg(bias + wn * 64 + col);
                    float c1 = acc[mt][j][half * 2 + 1] + __ldg(bias + wn * 64 + col + 1);
                    float2 o;
                    o.x = act ? leaky(c0) : c0;
                    o.y = act ? leaky(c1) : c1;
                    *(float2*)(po + col) = o;
                    if (pa) *(float2*)(pa + col) = o;
                }
            } else {
                const float id = __ldg(inv + gr);
                const float dg = __ldg(dis + gr);
                float* po = out + (size_t)gr * 128 + wn * 64;
                __half2* py = ybuf + (size_t)gr * 64 + wn * 32;
#pragma unroll
                for (int j = 0; j < 8; j++) {
                    const int col = j * 8 + tq * 2;
                    float xl0 = acc[mt][j][half * 2 + 0] + __ldg(bias + wn * 64 + col);
                    float xl1 = acc[mt][j][half * 2 + 1] + __ldg(bias + wn * 64 + col + 1);
                    float2 ini;
                    ini.x = relu_(xl0 + __ldg(root + wn * 64 + col)) * id;
                    ini.y = relu_(xl1 + __ldg(root + wn * 64 + col + 1)) * id;
                    *(float2*)(po + col) = ini;
                    py[col >> 1] = __floats2half2_rn(dg * relu_(xl0), dg * relu_(xl1));
                }
            }
        }
    }
}

// ---------------------------------------------------------------------------
// CSR gather-aggregate (pass B) + LayerNorm + LeakyReLU + residual.
// ---------------------------------------------------------------------------
__device__ __forceinline__ float4 gather_sum(const __half2* __restrict__ y,
                                             const int* __restrict__ src,
                                             int o, int k, int lane) {
    float4 na = make_float4(0.f, 0.f, 0.f, 0.f);
    int j = 0;
    for (; j + 2 <= k; j += 2) {
        const int s0 = __ldg(src + o + j);
        const int s1 = __ldg(src + o + j + 1);
        const uint2 v0 = *(const uint2*)(y + (size_t)s0 * 64 + lane * 2);
        const uint2 v1 = *(const uint2*)(y + (size_t)s1 * 64 + lane * 2);
        float2 a0 = __half22float2(*(const __half2*)&v0.x);
        float2 a1 = __half22float2(*(const __half2*)&v0.y);
        float2 b0 = __half22float2(*(const __half2*)&v1.x);
        float2 b1 = __half22float2(*(const __half2*)&v1.y);
        na.x += a0.x + b0.x;
        na.y += a0.y + b0.y;
        na.z += a1.x + b1.x;
        na.w += a1.y + b1.y;
    }
    if (j < k) {
        const int s0 = __ldg(src + o + j);
        const uint2 v0 = *(const uint2*)(y + (size_t)s0 * 64 + lane * 2);
        float2 a0 = __half22float2(*(const __half2*)&v0.x);
        float2 a1 = __half22float2(*(const __half2*)&v0.y);
        na.x += a0.x; na.y += a0.y; na.z += a1.x; na.w += a1.y;
    }
    return na;
}

__global__ void agg_ln_kernel(const float* __restrict__ init,
                              const __half2* __restrict__ y,
                              const int* __restrict__ offs,
                              const int* __restrict__ cnt,
                              const int* __restrict__ src,
                              const float* __restrict__ dis,
                              const float* __restrict__ g,
                              const float* __restrict__ b,
                              const float* __restrict__ hprev,
                              float* __restrict__ hnext, int hstride, int hofs,
                              float* __restrict__ aux, int aofs, int rows_aux,
                              int Nn, int obase) {
    const int c = blockIdx.x * 8 + (threadIdx.x >> 5);
    if (c >= Nn) return;
    const int lane = threadIdx.x & 31;

    float4 acc = ((const float4*)init)[(size_t)c * 32 + lane];
    const int o = __ldg(offs + obase + c);
    const int k = __ldg(cnt + obase + c);
    const float dc = __ldg(dis + c);
    float4 na = gather_sum(y, src, o, k, lane);
    acc.x += dc * na.x; acc.y += dc * na.y;
    acc.z += dc * na.z; acc.w += dc * na.w;

    float s1 = acc.x + acc.y + acc.z + acc.w;
#pragma unroll
    for (int off = 16; off > 0; off >>= 1) s1 += __shfl_xor_sync(0xffffffffu, s1, off);
    const float mu = s1 * (1.0f / 128.0f);
    float dx = acc.x - mu, dy = acc.y - mu, dz = acc.z - mu, dw = acc.w - mu;
    float q = dx * dx + dy * dy + dz * dz + dw * dw;
#pragma unroll
    for (int off = 16; off > 0; off >>= 1) q += __shfl_xor_sync(0xffffffffu, q, off);
    const float rstd = rsqrtf(q * (1.0f / 128.0f) + LN_EPS);

    float4 gg = ((const float4*)g)[lane];
    float4 bb = ((const float4*)b)[lane];
    float4 hp = ((const float4*)hprev)[(size_t)c * 32 + lane];
    float4 out;
    out.x = leaky(dx * rstd * gg.x + bb.x) + hp.x;
    out.y = leaky(dy * rstd * gg.y + bb.y) + hp.y;
    out.z = leaky(dz * rstd * gg.z + bb.z) + hp.z;
    out.w = leaky(dw * rstd * gg.w + bb.w) + hp.w;
    ((float4*)(hnext + (size_t)c * hstride + hofs))[lane] = out;
    if (aux && c < rows_aux)
        ((float4*)(aux + (size_t)c * 512 + aofs))[lane] = out;
}

// ---------------------------------------------------------------------------
// Launch
// ---------------------------------------------------------------------------
extern "C" void kernel_launch(void* const* d_in, const int* in_sizes, int n_in,
                              void* d_out, int out_size) {
    const float* x        = (const float*)d_in[0];
    const float* enc_w1   = (const float*)d_in[1];
    const float* enc_b1   = (const float*)d_in[2];
    const float* enc_w2   = (const float*)d_in[3];
    const float* enc_b2   = (const float*)d_in[4];
    const float* conv_w   = (const float*)d_in[5];
    const float* conv_b   = (const float*)d_in[6];
    const float* conv_rt  = (const float*)d_in[7];
    const float* reconv_w = (const float*)d_in[8];
    const float* reconv_b = (const float*)d_in[9];
    const float* reconv_rt= (const float*)d_in[10];
    const float* ln_g     = (const float*)d_in[11];
    const float* ln_b     = (const float*)d_in[12];
    const int*   eA       = (const int*)d_in[13];
    const int*   eB       = (const int*)d_in[14];

    const int N  = in_sizes[0] / 32;
    const int Ea = in_sizes[13] / 2;
    const int Eb = in_sizes[14] / 2;
    const int rows_out = out_size / 512;

    const int* rowsA = eA; const int* colsA = eA + Ea;
    const int* rowsB = eB; const int* colsB = eB + Eb;

    void* p;
    cudaGetSymbolAddress(&p, g_H);    float* H    = (float*)p;
    cudaGetSymbolAddress(&p, g_XL);   float* XL   = (float*)p;
    cudaGetSymbolAddress(&p, g_AGG);  float* AGG  = (float*)p;
    cudaGetSymbolAddress(&p, g_H1);   float* H1E  = (float*)p;
    cudaGetSymbolAddress(&p, g_YA);   __half2* YA = (__half2*)p;
    cudaGetSymbolAddress(&p, g_YB);   __half2* YB = (__half2*)p;
    cudaGetSymbolAddress(&p, g_disA); float* disA = (float*)p;
    cudaGetSymbolAddress(&p, g_disB); float* disB = (float*)p;
    cudaGetSymbolAddress(&p, g_invA); float* invA = (float*)p;
    cudaGetSymbolAddress(&p, g_invB); float* invB = (float*)p;
    cudaGetSymbolAddress(&p, g_icsr); int* icsr   = (int*)p;
    cudaGetSymbolAddress(&p, g_offs); int* offs   = (int*)p;
    cudaGetSymbolAddress(&p, g_src);  int* src    = (int*)p;
    cudaGetSymbolAddress(&p, g_bsums);int* bsums  = (int*)p;
    cudaGetSymbolAddress(&p, g_Bhi);  __nv_bfloat16* BH = (__nv_bfloat16*)p;
    cudaGetSymbolAddress(&p, g_Blo);  __nv_bfloat16* BL = (__nv_bfloat16*)p;

    int* rowcntA = icsr;
    int* rowcntB = icsr + NMAX;
    int* colcnt  = icsr + 2 * NMAX;
    int* cursor  = icsr + 4 * NMAX;

    const size_t hstride = (size_t)NMAX * EMB;
    float* dout = (float*)d_out;

    cudaFuncSetAttribute(gemm_tc_kernel,
                         cudaFuncAttributeMaxDynamicSharedMemorySize, SMEM_TC);

    // ---- weight prep ----
    prep_all_kernel<<<18 * 32, 256>>>(enc_w1, enc_w2, conv_w, reconv_w, BH, BL);

    // ---- CSR build + degrees ----
    zero_kernel<<<(6 * NMAX + 255) / 256, 256>>>(icsr, 6 * NMAX);
    hist2_kernel<<<(Ea + 255) / 256, 256>>>(rowsA, colsA, rowcntA, colcnt, Ea);
    hist2_kernel<<<(Eb + 255) / 256, 256>>>(rowsB, colsB, rowcntB, colcnt + NMAX, Eb);
    deg_fin_kernel<<<(N + 255) / 256, 256>>>(rowcntA, disA, invA, N);
    deg_fin_kernel<<<(N + 255) / 256, 256>>>(rowcntB, disB, invB, N);
    {
        const int n2 = 2 * NMAX;
        const int nb = (n2 + 1023) / 1024;
        scan_block_kernel<<<nb, 256>>>(colcnt, offs, bsums, n2);
        scan_sums_kernel<<<1, 512>>>(bsums, nb);
        scan_add_kernel<<<(n2 + 255) / 256, 256>>>(offs, bsums, n2);
    }
    fill_kernel<<<(Ea + 255) / 256, 256>>>(rowsA, colsA, offs, cursor, src, Ea, 0);
    fill_kernel<<<(Eb + 255) / 256, 256>>>(rowsB, colsB, offs, cursor, src, Eb, NMAX);

    const int tiles = (N + 127) / 128;

    // ---- encoder ----
    gemm_tc_kernel<<<tiles, 256, SMEM_TC>>>(x, 32, N,
        BH + 0 * 8192, BL + 0 * 8192, 1, 32, enc_b1, H1E, 256, 0, 1,
        nullptr, 0, 0, 0, nullptr, nullptr, nullptr, nullptr,
        nullptr, nullptr, nullptr, nullptr, nullptr, nullptr);
    gemm_tc_kernel<<<tiles, 256, SMEM_TC>>>(x, 32, N,
        BH + 1 * 8192, BL + 1 * 8192, 1, 32, enc_b1 + 128, H1E, 256, 128, 1,
        nullptr, 0, 0, 0, nullptr, nullptr, nullptr, nullptr,
        nullptr, nullptr, nullptr, nullptr, nullptr, nullptr);
    gemm_tc_kernel<<<tiles, 256, SMEM_TC>>>(H1E, 256, N,
        BH + 2 * 8192, BL + 2 * 8192, 4, 256, enc_b2, H, 128, 0, 1,
        dout, 0, rows_out, 0, nullptr, nullptr, nullptr, nullptr,
        nullptr, nullptr, nullptr, nullptr, nullptr, nullptr);

    // ---- GCN layers ----
    for (int l = 0; l < 3; l++) {
        const float* hl = H + (size_t)l * hstride;
        float* hn = H + (size_t)(l + 1) * hstride;
        const int last = (l == 2);

        // conv (edge set A): normal staging from hl; epilogue -> AGG init + YA
        gemm_tc_kernel<<<tiles, 256, SMEM_TC>>>(hl, 128, N,
            BH + (6 + 2 * l) * 8192, BL + (6 + 2 * l) * 8192, 2, 128,
            conv_b + l * EMB, AGG, 128, 0, 0,
            nullptr, 0, 0, 1, conv_rt + l * EMB, disA, invA, YA,
            nullptr, nullptr, nullptr, nullptr, nullptr, nullptr);

        // reconv (edge set B): FUSED staging (aggregate pass A on the fly);
        // epilogue -> XL init + YB
        gemm_tc_kernel<<<tiles, 256, SMEM_TC>>>(nullptr, 0, N,
            BH + (12 + 2 * l) * 8192, BL + (12 + 2 * l) * 8192, 2, 128,
            reconv_b + l * EMB, XL, 128, 0, 0,
            nullptr, 0, 0, 1, reconv_rt + l * EMB, disB, invB, YB,
            AGG, YA, offs, colcnt, src, disA);

        // pass-B aggregation + LN + leaky + residual
        if (!last) {
            agg_ln_kernel<<<(N + 7) / 8, 256>>>(XL, YB, offs, colcnt, src, disB,
                ln_g + l * EMB, ln_b + l * EMB, hl,
                hn, 128, 0, dout, (l + 1) * 128, rows_out, N, NMAX);
        } else {
            agg_ln_kernel<<<(rows_out + 7) / 8, 256>>>(XL, YB, offs, colcnt, src, disB,
                ln_g + l * EMB, ln_b + l * EMB, hl,
                dout, 512, 384, nullptr, 0, 0, rows_out, NMAX);
        }
    }
}

// round 12
// speedup vs baseline: 1.2616x; 1.2616x over previous
#include <cuda_runtime.h>
#include <cuda_bf16.h>
#include <cuda_fp16.h>
#include <cstddef>
#include <cstdint>

// ---------------------------------------------------------------------------
// Problem constants
// ---------------------------------------------------------------------------
#define NMAX   200000
#define EMAX   650000
#define EMB    128
#define ENC1   256
#define NEG_SLOPE 0.1f
#define LN_EPS 1e-5f

// ---------------------------------------------------------------------------
// Scratch (static __device__ arrays; no allocations allowed)
// ---------------------------------------------------------------------------
__device__ float g_H[4][(size_t)NMAX * EMB];   // h_list[0..3]
__device__ float g_AGG[(size_t)NMAX * EMB];    // pass-A aggregated output (fp32)
__device__ float g_H1[(size_t)NMAX * ENC1];    // encoder intermediate
__device__ __half2 g_YA[(size_t)NMAX * 64];    // fp16 messages, pass A
__device__ __half2 g_YB[(size_t)NMAX * 64];    // fp16 messages, pass B
__device__ __half2 g_IN[(size_t)NMAX * 64];    // fp16 init (self term), reused A/B
__device__ float g_disA[NMAX];
__device__ float g_disB[NMAX];
__device__ float g_invA[NMAX];
__device__ float g_invB[NMAX];
// CSR scratch: [0,N) rowcntA | [N,2N) rowcntB | [2N,4N) colcnt (A then B)
//              [4N,6N) cursors (A then B)
__device__ int g_icsr[6 * NMAX];
__device__ int g_offs[2 * NMAX];
__device__ int g_src[2 * EMAX];
__device__ int g_bsums[512];
// Prepped weight chunks: 18 chunks of [128 n x 64 k] bf16, XOR-swizzled, hi/lo.
__device__ __nv_bfloat16 g_Bhi[18 * 8192];
__device__ __nv_bfloat16 g_Blo[18 * 8192];

// ---------------------------------------------------------------------------
// Helpers
// ---------------------------------------------------------------------------
__device__ __forceinline__ float leaky(float v) {
    return v >= 0.0f ? v : NEG_SLOPE * v;
}
__device__ __forceinline__ float relu_(float v) { return fmaxf(v, 0.0f); }

__device__ __forceinline__ uint32_t smem_u32(const void* p) {
    uint32_t a;
    asm("{ .reg .u64 t; cvta.to.shared.u64 t, %1; cvt.u32.u64 %0, t; }"
        : "=r"(a) : "l"(p));
    return a;
}

__device__ __forceinline__ void ldsm4(uint32_t* r, uint32_t addr) {
    asm volatile("ldmatrix.sync.aligned.m8n8.x4.shared.b16 {%0,%1,%2,%3}, [%4];"
                 : "=r"(r[0]), "=r"(r[1]), "=r"(r[2]), "=r"(r[3]) : "r"(addr));
}

__device__ __forceinline__ void mma16816(float* c, const uint32_t* a,
                                         uint32_t b0, uint32_t b1) {
    asm volatile(
        "mma.sync.aligned.m16n8k16.row.col.f32.bf16.bf16.f32 "
        "{%0,%1,%2,%3}, {%4,%5,%6,%7}, {%8,%9}, {%0,%1,%2,%3};"
        : "+f"(c[0]), "+f"(c[1]), "+f"(c[2]), "+f"(c[3])
        : "r"(a[0]), "r"(a[1]), "r"(a[2]), "r"(a[3]), "r"(b0), "r"(b1));
}

// fp32x4 -> swizzled bf16 hi/lo store (packed converts)
__device__ __forceinline__ void store_hilo(char* smbase, int off, float4 v) {
    __nv_bfloat162 h01 = __float22bfloat162_rn(make_float2(v.x, v.y));
    __nv_bfloat162 h23 = __float22bfloat162_rn(make_float2(v.z, v.w));
    float2 hf01 = __bfloat1622float2(h01);
    float2 hf23 = __bfloat1622float2(h23);
    __nv_bfloat162 l01 = __float22bfloat162_rn(make_float2(v.x - hf01.x, v.y - hf01.y));
    __nv_bfloat162 l23 = __float22bfloat162_rn(make_float2(v.z - hf23.x, v.w - hf23.y));
    uint2 hi = make_uint2(*reinterpret_cast<uint32_t*>(&h01),
                          *reinterpret_cast<uint32_t*>(&h23));
    uint2 lo = make_uint2(*reinterpret_cast<uint32_t*>(&l01),
                          *reinterpret_cast<uint32_t*>(&l23));
    *(uint2*)(smbase + 0     + off) = hi;   // SM_A_HI == 0
    *(uint2*)(smbase + 16384 + off) = lo;   // SM_A_LO == 16384
}

// ---------------------------------------------------------------------------
// CSR build kernels
// ---------------------------------------------------------------------------
__global__ void zero_kernel(int* p, int n) {
    int i = blockIdx.x * blockDim.x + threadIdx.x;
    if (i < n) p[i] = 0;
}

__global__ void hist2_kernel(const int* __restrict__ rows,
                             const int* __restrict__ cols,
                             int* __restrict__ rowcnt,
                             int* __restrict__ colcnt, int E) {
    int e = blockIdx.x * blockDim.x + threadIdx.x;
    if (e >= E) return;
    atomicAdd(&rowcnt[rows[e]], 1);
    atomicAdd(&colcnt[cols[e]], 1);
}

__global__ void deg_fin_kernel(const int* __restrict__ cnt,
                               float* __restrict__ dis,
                               float* __restrict__ inv, int n) {
    int i = blockIdx.x * blockDim.x + threadIdx.x;
    if (i < n) {
        float d = (float)(cnt[i] + 1);
        dis[i] = rsqrtf(d);
        inv[i] = 1.0f / d;
    }
}

__global__ void scan_block_kernel(const int* __restrict__ in, int* __restrict__ out,
                                  int* __restrict__ bsums, int n) {
    __shared__ int sh[256];
    const int base = blockIdx.x * 1024;
    const int t = threadIdx.x;
    int v[4]; int s = 0;
#pragma unroll
    for (int j = 0; j < 4; j++) {
        int i = base + t * 4 + j;
        v[j] = (i < n) ? in[i] : 0;
        s += v[j];
    }
    sh[t] = s;
    __syncthreads();
    for (int off = 1; off < 256; off <<= 1) {
        int x = (t >= off) ? sh[t - off] : 0;
        __syncthreads();
        sh[t] += x;
        __syncthreads();
    }
    int run = (t > 0) ? sh[t - 1] : 0;
    if (t == 255) bsums[blockIdx.x] = sh[255];
#pragma unroll
    for (int j = 0; j < 4; j++) {
        int i = base + t * 4 + j;
        if (i < n) out[i] = run;
        run += v[j];
    }
}

__global__ void scan_sums_kernel(int* bsums, int nb) {
    __shared__ int sh[512];
    int t = threadIdx.x;
    sh[t] = (t < nb) ? bsums[t] : 0;
    __syncthreads();
    for (int off = 1; off < 512; off <<= 1) {
        int x = (t >= off) ? sh[t - off] : 0;
        __syncthreads();
        sh[t] += x;
        __syncthreads();
    }
    if (t < nb) bsums[t] = (t > 0) ? sh[t - 1] : 0;
}

__global__ void scan_add_kernel(int* __restrict__ out, const int* __restrict__ bsums,
                                int n) {
    int i = blockIdx.x * blockDim.x + threadIdx.x;
    if (i < n) out[i] += bsums[i >> 10];
}

__global__ void fill_kernel(const int* __restrict__ rows, const int* __restrict__ cols,
                            const int* __restrict__ offs, int* __restrict__ cursor,
                            int* __restrict__ src, int E, int obase) {
    int e = blockIdx.x * blockDim.x + threadIdx.x;
    if (e >= E) return;
    int c = cols[e];
    int pos = offs[obase + c] + atomicAdd(&cursor[obase + c], 1);
    src[pos] = rows[e];
}

// ---------------------------------------------------------------------------
// Merged weight prep: 18 chunks of [128n x 64k], swizzled bf16 hi/lo
// ---------------------------------------------------------------------------
__global__ void prep_all_kernel(const float* __restrict__ enc_w1,
                                const float* __restrict__ enc_w2,
                                const float* __restrict__ conv_w,
                                const float* __restrict__ reconv_w,
                                __nv_bfloat16* __restrict__ BH,
                                __nv_bfloat16* __restrict__ BL) {
    const int chunk = blockIdx.x >> 5;
    const int idx = (blockIdx.x & 31) * 256 + threadIdx.x;
    const int n = idx >> 6;
    const int k = idx & 63;
    const float* W; int ldn, k0, n0, kcount;
    if (chunk < 2)      { W = enc_w1; ldn = 256; k0 = 0; n0 = chunk * 128; kcount = 32; }
    else if (chunk < 6) { W = enc_w2; ldn = 128; k0 = (chunk - 2) * 64; n0 = 0; kcount = 64; }
    else if (chunk < 12) {
        int l = (chunk - 6) >> 1, c = (chunk - 6) & 1;
        W = conv_w + (size_t)l * 16384; ldn = 128; k0 = c * 64; n0 = 0; kcount = 64;
    } else {
        int l = (chunk - 12) >> 1, c = (chunk - 12) & 1;
        W = reconv_w + (size_t)l * 16384; ldn = 128; k0 = c * 64; n0 = 0; kcount = 64;
    }
    float v = (k < kcount) ? W[(size_t)(k0 + k) * ldn + n0 + n] : 0.0f;
    __nv_bfloat16 h = __float2bfloat16(v);
    __nv_bfloat16 l = __float2bfloat16(v - __bfloat162float(h));
    int off = n * 128 + ((k * 2) ^ ((n & 7) << 4));
    BH[(size_t)chunk * 8192 + (off >> 1)] = h;
    BL[(size_t)chunk * 8192 + (off >> 1)] = l;
}

// ---------------------------------------------------------------------------
// Tensor-core GEMM (mma.sync bf16 3-split): d = A[M,KV] @ W + bias
//  mode 0: out[gr*ostride+colofs+n] = act? leaky(d) : d
//          if (aux && gr<rows_aux) also aux[gr*512+aofs+n]
//  mode 1 (GCN prep): ibuf[gr][n] = half( relu(d+root[n]) * inv[gr] )  (init)
//                     ybuf[gr][n] = half( dis[gr] * relu(d) )          (message)
// ---------------------------------------------------------------------------
#define SM_A_HI 0
#define SM_A_LO 16384
#define SM_B_HI 32768
#define SM_B_LO 49152
#define SMEM_TC 65536

__global__ void __launch_bounds__(256, 2)
gemm_tc_kernel(const float* __restrict__ A, int lda, int M,
               const __nv_bfloat16* __restrict__ BhiG,
               const __nv_bfloat16* __restrict__ BloG,
               int kchunks, int KV,
               const float* __restrict__ bias,
               float* __restrict__ out, int ostride, int colofs, int act,
               float* __restrict__ aux, int aofs, int rows_aux,
               int mode,
               const float* __restrict__ root,
               const float* __restrict__ dis,
               const float* __restrict__ inv,
               __half2* __restrict__ ybuf,
               __half2* __restrict__ ibuf) {
    extern __shared__ char sm[];
    const uint32_t sb = smem_u32(sm);
    const int tid = threadIdx.x;
    const int w = tid >> 5;
    const int lane = tid & 31;
    const int wm = w & 3;
    const int wn = w >> 2;
    const int row0 = blockIdx.x * 128;

    float acc[2][8][4];
#pragma unroll
    for (int a = 0; a < 2; a++)
#pragma unroll
        for (int b = 0; b < 8; b++)
#pragma unroll
            for (int c = 0; c < 4; c++) acc[a][b][c] = 0.0f;

    for (int ck = 0; ck < kchunks; ck++) {
        const int kbase = ck * 64;
        int kcols = KV - kbase; if (kcols > 64) kcols = 64;
        const int ksteps = (kcols + 15) >> 4;

        // ---- stage B chunk ----
        {
            const float4* shg = (const float4*)(BhiG + (size_t)ck * 8192);
            const float4* slg = (const float4*)(BloG + (size_t)ck * 8192);
            float4* dh = (float4*)(sm + SM_B_HI);
            float4* dl = (float4*)(sm + SM_B_LO);
            for (int i = tid; i < 1024; i += 256) { dh[i] = shg[i]; dl[i] = slg[i]; }
        }

        // ---- stage A chunk [128 x 64] fp32 -> bf16 hi/lo, swizzled ----
#pragma unroll
        for (int i = 0; i < 8; i++) {
            const int idx = tid + i * 256;
            const int r = idx >> 4;
            const int c4 = idx & 15;
            float4 v = make_float4(0.f, 0.f, 0.f, 0.f);
            const int gr = row0 + r;
            if (gr < M && c4 * 4 < kcols)
                v = *(const float4*)(A + (size_t)gr * lda + kbase + c4 * 4);
            int off = r * 128 + ((c4 * 8) ^ ((r & 7) << 4));
            store_hilo(sm, off, v);
        }
        __syncthreads();

        // ---- compute ----
        for (int ks = 0; ks < ksteps; ks++) {
            uint32_t ah[2][4], al[2][4];
            {
                const int rr = (lane & 15);
                const int colb = ks * 32 + (lane & 16);
#pragma unroll
                for (int mt = 0; mt < 2; mt++) {
                    const int row = wm * 32 + mt * 16 + rr;
                    const uint32_t ad = (uint32_t)(row * 128 + (colb ^ ((row & 7) << 4)));
                    ldsm4(ah[mt], sb + SM_A_HI + ad);
                    ldsm4(al[mt], sb + SM_A_LO + ad);
                }
            }
#pragma unroll
            for (int np = 0; np < 4; np++) {
                const int nb = wn * 64 + np * 16;
                const int n = nb + (lane & 7) + ((lane & 16) >> 1);
                const int colb = ks * 32 + ((lane & 8) << 1);
                const uint32_t bd = (uint32_t)(n * 128 + (colb ^ ((n & 7) << 4)));
                uint32_t bh[4], bl[4];
                ldsm4(bh, sb + SM_B_HI + bd);
                ldsm4(bl, sb + SM_B_LO + bd);
#pragma unroll
                for (int mt = 0; mt < 2; mt++) {
#pragma unroll
                    for (int nt = 0; nt < 2; nt++) {
                        float* c = acc[mt][np * 2 + nt];
                        mma16816(c, ah[mt], bh[nt * 2], bh[nt * 2 + 1]);
                        mma16816(c, ah[mt], bl[nt * 2], bl[nt * 2 + 1]);
                        mma16816(c, al[mt], bh[nt * 2], bh[nt * 2 + 1]);
                    }
                }
            }
        }
        __syncthreads();
    }

    // ---- epilogue ----
    const int quad = lane >> 2;
    const int tq = lane & 3;
#pragma unroll
    for (int mt = 0; mt < 2; mt++) {
#pragma unroll
        for (int half = 0; half < 2; half++) {
            const int gr = row0 + wm * 32 + mt * 16 + half * 8 + quad;
            if (gr >= M) continue;
            if (mode == 0) {
                float* po = out + (size_t)gr * ostride + colofs + wn * 64;
                float* pa = (aux && gr < rows_aux)
                          ? aux + (size_t)gr * 512 + aofs + wn * 64 : nullptr;
#pragma unroll
                for (int j = 0; j < 8; j++) {
                    const int col = j * 8 + tq * 2;
                    float c0 = acc[mt][j][half * 2 + 0] + __ldg(bias + wn * 64 + col);
                    float c1 = acc[mt][j][half * 2 + 1] + __ldg(bias + wn * 64 + col + 1);
                    float2 o;
                    o.x = act ? leaky(c0) : c0;
                    o.y = act ? leaky(c1) : c1;
                    *(float2*)(po + col) = o;
                    if (pa) *(float2*)(pa + col) = o;
                }
            } else {
                const float id = __ldg(inv + gr);
                const float dg = __ldg(dis + gr);
                __half2* pi = ibuf + (size_t)gr * 64 + wn * 32;
                __half2* py = ybuf + (size_t)gr * 64 + wn * 32;
#pragma unroll
                for (int j = 0; j < 8; j++) {
                    const int col = j * 8 + tq * 2;
                    float xl0 = acc[mt][j][half * 2 + 0] + __ldg(bias + wn * 64 + col);
                    float xl1 = acc[mt][j][half * 2 + 1] + __ldg(bias + wn * 64 + col + 1);
                    pi[col >> 1] = __floats2half2_rn(
                        relu_(xl0 + __ldg(root + wn * 64 + col)) * id,
                        relu_(xl1 + __ldg(root + wn * 64 + col + 1)) * id);
                    py[col >> 1] = __floats2half2_rn(dg * relu_(xl0), dg * relu_(xl1));
                }
            }
        }
    }
}

// ---------------------------------------------------------------------------
// CSR gather helpers
// ---------------------------------------------------------------------------
__device__ __forceinline__ float4 gather_sum(const __half2* __restrict__ y,
                                             const int* __restrict__ src,
                                             int o, int k, int lane) {
    float4 na = make_float4(0.f, 0.f, 0.f, 0.f);
    int j = 0;
    for (; j + 2 <= k; j += 2) {
        const int s0 = __ldg(src + o + j);
        const int s1 = __ldg(src + o + j + 1);
        const uint2 v0 = *(const uint2*)(y + (size_t)s0 * 64 + lane * 2);
        const uint2 v1 = *(const uint2*)(y + (size_t)s1 * 64 + lane * 2);
        float2 a0 = __half22float2(*(const __half2*)&v0.x);
        float2 a1 = __half22float2(*(const __half2*)&v0.y);
        float2 b0 = __half22float2(*(const __half2*)&v1.x);
        float2 b1 = __half22float2(*(const __half2*)&v1.y);
        na.x += a0.x + b0.x;
        na.y += a0.y + b0.y;
        na.z += a1.x + b1.x;
        na.w += a1.y + b1.y;
    }
    if (j < k) {
        const int s0 = __ldg(src + o + j);
        const uint2 v0 = *(const uint2*)(y + (size_t)s0 * 64 + lane * 2);
        float2 a0 = __half22float2(*(const __half2*)&v0.x);
        float2 a1 = __half22float2(*(const __half2*)&v0.y);
        na.x += a0.x; na.y += a0.y; na.z += a1.x; na.w += a1.y;
    }
    return na;
}

__device__ __forceinline__ float4 load_init_h(const __half2* __restrict__ ibuf,
                                              int c, int lane) {
    const uint2 iv = *(const uint2*)(ibuf + (size_t)c * 64 + lane * 2);
    float2 i0 = __half22float2(*(const __half2*)&iv.x);
    float2 i1 = __half22float2(*(const __half2*)&iv.y);
    return make_float4(i0.x, i0.y, i1.x, i1.y);
}

// ---------------------------------------------------------------------------
// Pass-A aggregation: agg[c] = init[c] + dis[c] * sum YA[src]   (fp32 out)
// ---------------------------------------------------------------------------
__global__ void agg_kernel(const __half2* __restrict__ ibuf,
                           const __half2* __restrict__ y,
                           const int* __restrict__ offs,
                           const int* __restrict__ cnt,
                           const int* __restrict__ src,
                           const float* __restrict__ dis,
                           float* __restrict__ agg, int Nn, int obase) {
    const int c = blockIdx.x * 8 + (threadIdx.x >> 5);
    if (c >= Nn) return;
    const int lane = threadIdx.x & 31;

    float4 acc = load_init_h(ibuf, c, lane);
    const int o = __ldg(offs + obase + c);
    const int k = __ldg(cnt + obase + c);
    const float dc = __ldg(dis + c);
    float4 na = gather_sum(y, src, o, k, lane);
    acc.x += dc * na.x; acc.y += dc * na.y;
    acc.z += dc * na.z; acc.w += dc * na.w;
    ((float4*)agg)[(size_t)c * 32 + lane] = acc;
}

// ---------------------------------------------------------------------------
// Pass-B aggregation + LayerNorm + LeakyReLU + residual.
// ---------------------------------------------------------------------------
__global__ void agg_ln_kernel(const __half2* __restrict__ ibuf,
                              const __half2* __restrict__ y,
                              const int* __restrict__ offs,
                              const int* __restrict__ cnt,
                              const int* __restrict__ src,
                              const float* __restrict__ dis,
                              const float* __restrict__ g,
                              const float* __restrict__ b,
                              const float* __restrict__ hprev,
                              float* __restrict__ hnext, int hstride, int hofs,
                              float* __restrict__ aux, int aofs, int rows_aux,
                              int Nn, int obase) {
    const int c = blockIdx.x * 8 + (threadIdx.x >> 5);
    if (c >= Nn) return;
    const int lane = threadIdx.x & 31;

    float4 acc = load_init_h(ibuf, c, lane);
    const int o = __ldg(offs + obase + c);
    const int k = __ldg(cnt + obase + c);
    const float dc = __ldg(dis + c);
    float4 na = gather_sum(y, src, o, k, lane);
    acc.x += dc * na.x; acc.y += dc * na.y;
    acc.z += dc * na.z; acc.w += dc * na.w;

    float s1 = acc.x + acc.y + acc.z + acc.w;
#pragma unroll
    for (int off = 16; off > 0; off >>= 1) s1 += __shfl_xor_sync(0xffffffffu, s1, off);
    const float mu = s1 * (1.0f / 128.0f);
    float dx = acc.x - mu, dy = acc.y - mu, dz = acc.z - mu, dw = acc.w - mu;
    float q = dx * dx + dy * dy + dz * dz + dw * dw;
#pragma unroll
    for (int off = 16; off > 0; off >>= 1) q += __shfl_xor_sync(0xffffffffu, q, off);
    const float rstd = rsqrtf(q * (1.0f / 128.0f) + LN_EPS);

    float4 gg = ((const float4*)g)[lane];
    float4 bb = ((const float4*)b)[lane];
    float4 hp = ((const float4*)hprev)[(size_t)c * 32 + lane];
    float4 out;
    out.x = leaky(dx * rstd * gg.x + bb.x) + hp.x;
    out.y = leaky(dy * rstd * gg.y + bb.y) + hp.y;
    out.z = leaky(dz * rstd * gg.z + bb.z) + hp.z;
    out.w = leaky(dw * rstd * gg.w + bb.w) + hp.w;
    ((float4*)(hnext + (size_t)c * hstride + hofs))[lane] = out;
    if (aux && c < rows_aux)
        ((float4*)(aux + (size_t)c * 512 + aofs))[lane] = out;
}

// ---------------------------------------------------------------------------
// Launch
// ---------------------------------------------------------------------------
extern "C" void kernel_launch(void* const* d_in, const int* in_sizes, int n_in,
                              void* d_out, int out_size) {
    const float* x        = (const float*)d_in[0];
    const float* enc_w1   = (const float*)d_in[1];
    const float* enc_b1   = (const float*)d_in[2];
    const float* enc_w2   = (const float*)d_in[3];
    const float* enc_b2   = (const float*)d_in[4];
    const float* conv_w   = (const float*)d_in[5];
    const float* conv_b   = (const float*)d_in[6];
    const float* conv_rt  = (const float*)d_in[7];
    const float* reconv_w = (const float*)d_in[8];
    const float* reconv_b = (const float*)d_in[9];
    const float* reconv_rt= (const float*)d_in[10];
    const float* ln_g     = (const float*)d_in[11];
    const float* ln_b     = (const float*)d_in[12];
    const int*   eA       = (const int*)d_in[13];
    const int*   eB       = (const int*)d_in[14];

    const int N  = in_sizes[0] / 32;
    const int Ea = in_sizes[13] / 2;
    const int Eb = in_sizes[14] / 2;
    const int rows_out = out_size / 512;

    const int* rowsA = eA; const int* colsA = eA + Ea;
    const int* rowsB = eB; const int* colsB = eB + Eb;

    void* p;
    cudaGetSymbolAddress(&p, g_H);    float* H    = (float*)p;
    cudaGetSymbolAddress(&p, g_AGG);  float* AGG  = (float*)p;
    cudaGetSymbolAddress(&p, g_H1);   float* H1E  = (float*)p;
    cudaGetSymbolAddress(&p, g_YA);   __half2* YA = (__half2*)p;
    cudaGetSymbolAddress(&p, g_YB);   __half2* YB = (__half2*)p;
    cudaGetSymbolAddress(&p, g_IN);   __half2* IN = (__half2*)p;
    cudaGetSymbolAddress(&p, g_disA); float* disA = (float*)p;
    cudaGetSymbolAddress(&p, g_disB); float* disB = (float*)p;
    cudaGetSymbolAddress(&p, g_invA); float* invA = (float*)p;
    cudaGetSymbolAddress(&p, g_invB); float* invB = (float*)p;
    cudaGetSymbolAddress(&p, g_icsr); int* icsr   = (int*)p;
    cudaGetSymbolAddress(&p, g_offs); int* offs   = (int*)p;
    cudaGetSymbolAddress(&p, g_src);  int* src    = (int*)p;
    cudaGetSymbolAddress(&p, g_bsums);int* bsums  = (int*)p;
    cudaGetSymbolAddress(&p, g_Bhi);  __nv_bfloat16* BH = (__nv_bfloat16*)p;
    cudaGetSymbolAddress(&p, g_Blo);  __nv_bfloat16* BL = (__nv_bfloat16*)p;

    int* rowcntA = icsr;
    int* rowcntB = icsr + NMAX;
    int* colcnt  = icsr + 2 * NMAX;
    int* cursor  = icsr + 4 * NMAX;

    const size_t hstride = (size_t)NMAX * EMB;
    float* dout = (float*)d_out;

    cudaFuncSetAttribute(gemm_tc_kernel,
                         cudaFuncAttributeMaxDynamicSharedMemorySize, SMEM_TC);

    // ---- side stream for the CSR build (overlaps with encoder GEMMs) ----
    static cudaStream_t s2 = nullptr;
    static cudaEvent_t ev_fork = nullptr, ev_join = nullptr;
    if (!s2) {
        cudaStreamCreateWithFlags(&s2, cudaStreamNonBlocking);
        cudaEventCreateWithFlags(&ev_fork, cudaEventDisableTiming);
        cudaEventCreateWithFlags(&ev_join, cudaEventDisableTiming);
    }

    cudaEventRecord(ev_fork, 0);
    cudaStreamWaitEvent(s2, ev_fork, 0);

    // ---- CSR build + degrees (side stream) ----
    zero_kernel<<<(6 * NMAX + 255) / 256, 256, 0, s2>>>(icsr, 6 * NMAX);
    hist2_kernel<<<(Ea + 255) / 256, 256, 0, s2>>>(rowsA, colsA, rowcntA, colcnt, Ea);
    hist2_kernel<<<(Eb + 255) / 256, 256, 0, s2>>>(rowsB, colsB, rowcntB,
                                                   colcnt + NMAX, Eb);
    deg_fin_kernel<<<(N + 255) / 256, 256, 0, s2>>>(rowcntA, disA, invA, N);
    deg_fin_kernel<<<(N + 255) / 256, 256, 0, s2>>>(rowcntB, disB, invB, N);
    {
        const int n2 = 2 * NMAX;
        const int nb = (n2 + 1023) / 1024;
        scan_block_kernel<<<nb, 256, 0, s2>>>(colcnt, offs, bsums, n2);
        scan_sums_kernel<<<1, 512, 0, s2>>>(bsums, nb);
        scan_add_kernel<<<(n2 + 255) / 256, 256, 0, s2>>>(offs, bsums, n2);
    }
    fill_kernel<<<(Ea + 255) / 256, 256, 0, s2>>>(rowsA, colsA, offs, cursor, src,
                                                  Ea, 0);
    fill_kernel<<<(Eb + 255) / 256, 256, 0, s2>>>(rowsB, colsB, offs, cursor, src,
                                                  Eb, NMAX);
    cudaEventRecord(ev_join, s2);

    // ---- weight prep + encoder (main stream, concurrent with CSR build) ----
    prep_all_kernel<<<18 * 32, 256>>>(enc_w1, enc_w2, conv_w, reconv_w, BH, BL);

    const int tiles = (N + 127) / 128;

    gemm_tc_kernel<<<tiles, 256, SMEM_TC>>>(x, 32, N,
        BH + 0 * 8192, BL + 0 * 8192, 1, 32, enc_b1, H1E, 256, 0, 1,
        nullptr, 0, 0, 0, nullptr, nullptr, nullptr, nullptr, nullptr);
    gemm_tc_kernel<<<tiles, 256, SMEM_TC>>>(x, 32, N,
        BH + 1 * 8192, BL + 1 * 8192, 1, 32, enc_b1 + 128, H1E, 256, 128, 1,
        nullptr, 0, 0, 0, nullptr, nullptr, nullptr, nullptr, nullptr);
    gemm_tc_kernel<<<tiles, 256, SMEM_TC>>>(H1E, 256, N,
        BH + 2 * 8192, BL + 2 * 8192, 4, 256, enc_b2, H, 128, 0, 1,
        dout, 0, rows_out, 0, nullptr, nullptr, nullptr, nullptr, nullptr);

    // join: GCN layers need the CSR
    cudaStreamWaitEvent(0, ev_join, 0);

    // ---- GCN layers ----
    for (int l = 0; l < 3; l++) {
        const float* hl = H + (size_t)l * hstride;
        float* hn = H + (size_t)(l + 1) * hstride;
        const int last = (l == 2);

        // conv (edge set A): GEMM -> IN (half init) + YA
        gemm_tc_kernel<<<tiles, 256, SMEM_TC>>>(hl, 128, N,
            BH + (6 + 2 * l) * 8192, BL + (6 + 2 * l) * 8192, 2, 128,
            conv_b + l * EMB, nullptr, 0, 0, 0,
            nullptr, 0, 0, 1, conv_rt + l * EMB, disA, invA, YA, IN);
        agg_kernel<<<(N + 7) / 8, 256>>>(IN, YA, offs, colcnt, src, disA, AGG, N, 0);

        // reconv (edge set B): GEMM reads AGG -> IN (half init, reused) + YB
        gemm_tc_kernel<<<tiles, 256, SMEM_TC>>>(AGG, 128, N,
            BH + (12 + 2 * l) * 8192, BL + (12 + 2 * l) * 8192, 2, 128,
            reconv_b + l * EMB, nullptr, 0, 0, 0,
            nullptr, 0, 0, 1, reconv_rt + l * EMB, disB, invB, YB, IN);

        if (!last) {
            agg_ln_kernel<<<(N + 7) / 8, 256>>>(IN, YB, offs, colcnt, src, disB,
                ln_g + l * EMB, ln_b + l * EMB, hl,
                hn, 128, 0, dout, (l + 1) * 128, rows_out, N, NMAX);
        } else {
            agg_ln_kernel<<<(rows_out + 7) / 8, 256>>>(IN, YB, offs, colcnt, src, disB,
                ln_g + l * EMB, ln_b + l * EMB, hl,
                dout, 512, 384, nullptr, 0, 0, rows_out, NMAX);
        }
    }
}